// round 10
// baseline (speedup 1.0000x reference)
#include <cuda_runtime.h>
#include <cuda_bf16.h>
#include <cstdint>

#define BATCH 8
#define C1    128
#define C2    256
#define HIN   160
#define HO    80
#define SPIX  6400
#define NPIX  51200
#define K1    1152
#define K3    2304

// -------- scratch (device globals; no runtime allocation) --------
__device__ float g_h  [BATCH*SPIX*C2];   // NHWC: [b][pixel][ci]
__device__ float g_off[BATCH*18*SPIX];   // offsets (NCHW)
__device__ __nv_bfloat16 g_w1h[C2*K1];   // conv1 weights, k=tap*128+ci, hi
__device__ __nv_bfloat16 g_w1l[C2*K1];   // lo
__device__ __nv_bfloat16 g_wdh[C2*K3];   // deform weights, k=tap*256+ci, hi
__device__ __nv_bfloat16 g_wdl[C2*K3];   // lo

// -------- helpers --------
__device__ __forceinline__ uint32_t smem_u32(const void* p){
  uint32_t a;
  asm("{ .reg .u64 t; cvta.to.shared.u64 t, %1; cvt.u32.u64 %0, t; }" : "=r"(a) : "l"(p));
  return a;
}
#define SWZ(o) ((o) ^ (((o)>>3)&0x70))

__device__ __forceinline__ void ldsm4(uint32_t* r, uint32_t addr){
  asm volatile("ldmatrix.sync.aligned.m8n8.x4.shared.b16 {%0,%1,%2,%3}, [%4];"
    : "=r"(r[0]),"=r"(r[1]),"=r"(r[2]),"=r"(r[3]) : "r"(addr));
}
__device__ __forceinline__ void ldsm2(uint32_t* r, uint32_t addr){
  asm volatile("ldmatrix.sync.aligned.m8n8.x2.shared.b16 {%0,%1}, [%2];"
    : "=r"(r[0]),"=r"(r[1]) : "r"(addr));
}
__device__ __forceinline__ void mma16816(float* d, const uint32_t* a, const uint32_t* b){
  asm volatile("mma.sync.aligned.m16n8k16.row.col.f32.bf16.bf16.f32 "
    "{%0,%1,%2,%3}, {%4,%5,%6,%7}, {%8,%9}, {%0,%1,%2,%3};"
    : "+f"(d[0]), "+f"(d[1]), "+f"(d[2]), "+f"(d[3])
    : "r"(a[0]), "r"(a[1]), "r"(a[2]), "r"(a[3]), "r"(b[0]), "r"(b[1]));
}

union Pack8 { unsigned short s[8]; uint4 v; };

__device__ __forceinline__ float silu_f(float v) {
  return __fdividef(v, 1.0f + __expf(-v));
}
__device__ __forceinline__ void split_bf16(float v, unsigned short& h, unsigned short& l){
  __nv_bfloat16 hh = __float2bfloat16(v);
  float hf = __bfloat162float(hh);
  __nv_bfloat16 ll = __float2bfloat16(v - hf);
  h = __bfloat16_as_ushort(hh);
  l = __bfloat16_as_ushort(ll);
}

// SMEM layout (byte offsets within dynamic smem)
#define SM_W    0        // weight tile: 256 rows x 128B hi, then lo
#define W_LO    32768
#define SM_P    65536    // pixel tile: 128 rows x 128B hi, then lo
#define P_LO    16384
#define SM_BN   98304    // scale[256] + shift[256] (2KB)
#define SM_META 100352   // conv1: ih[128], iw[128]
#define SM_TOF  100352             // deform: t_off 9*128*16B
#define SM_TWT  (100352+18432)     // deform: t_wt  9*128*16B
#define SMEM_CONV1  101376
#define SMEM_DEFORM 137216

// =====================================================================
// Prep: convert+reorder weights to bf16 hi/lo, k = tap*Cin + ci
// =====================================================================
__global__ void prep_kernel(const float* __restrict__ w1, const float* __restrict__ wd)
{
  int stride = gridDim.x * blockDim.x;
  for (int i = blockIdx.x*blockDim.x + threadIdx.x; i < C2*K1; i += stride) {
    int co = i / K1, t = i - co*K1, tap = t >> 7, ci = t & 127;
    float v = w1[(co*C1 + ci)*9 + tap];
    unsigned short h, l; split_bf16(v, h, l);
    g_w1h[i] = __ushort_as_bfloat16(h);
    g_w1l[i] = __ushort_as_bfloat16(l);
  }
  for (int i = blockIdx.x*blockDim.x + threadIdx.x; i < C2*K3; i += stride) {
    int co = i / K3, t = i - co*K3, tap = t >> 8, ci = t & 255;
    float v = wd[(co*C2 + ci)*9 + tap];
    unsigned short h, l; split_bf16(v, h, l);
    g_wdh[i] = __ushort_as_bfloat16(h);
    g_wdl[i] = __ushort_as_bfloat16(l);
  }
}

// =====================================================================
// Generic chunk MMA: K=64 (4 ksteps). M operand via ldsm4 (row-major rows),
// N operand via ldsm2. 3-product bf16 hi/lo split.
// =====================================================================
template<int MT, int NT>
__device__ __forceinline__ void chunk_mma(uint32_t sb,
    uint32_t moff, uint32_t mlo, uint32_t noff, uint32_t nlo,
    int mrow0, int nrow0, int lane, float d[MT][NT][4])
{
  #pragma unroll
  for (int ks = 0; ks < 4; ks++) {
    uint32_t bh[NT][2], bl[NT][2];
    const uint32_t bcol = ks*32 + ((lane >> 3) & 1) * 16;
    #pragma unroll
    for (int nt = 0; nt < NT; nt++) {
      uint32_t bo = SWZ((uint32_t)(nrow0 + nt*8 + (lane & 7)) * 128 + bcol);
      ldsm2(bh[nt], sb + noff + bo);
      ldsm2(bl[nt], sb + noff + nlo + bo);
    }
    const uint32_t acol = ks*32 + ((lane >> 4) & 1) * 16;
    #pragma unroll
    for (int mt = 0; mt < MT; mt++) {
      uint32_t ah[4], al[4];
      uint32_t ao = SWZ((uint32_t)(mrow0 + mt*16 + (lane & 15)) * 128 + acol);
      ldsm4(ah, sb + moff + ao);
      ldsm4(al, sb + moff + mlo + ao);
      #pragma unroll
      for (int nt = 0; nt < NT; nt++) {
        mma16816(d[mt][nt], ah, bh[nt]);
        mma16816(d[mt][nt], ah, bl[nt]);
        mma16816(d[mt][nt], al, bh[nt]);
      }
    }
  }
}

// Weight tile loader: 256 rows x 64 k (hi+lo), 128B rows, swizzled
__device__ __forceinline__ void ld_W_chunk(char* smem,
    const __nv_bfloat16* wh, const __nv_bfloat16* wl, int K, int k0, int tid)
{
  #pragma unroll
  for (int i = 0; i < 4; i++) {
    int e = tid + i*512;              // 0..2047
    int row = e >> 3, col = e & 7;
    size_t sbyte = ((size_t)row * K + k0) * 2 + col * 16;
    uint32_t doff = SWZ((uint32_t)(row*128 + col*16));
    *(uint4*)(smem + SM_W + doff)        = *(const uint4*)((const char*)wh + sbyte);
    *(uint4*)(smem + SM_W + W_LO + doff) = *(const uint4*)((const char*)wl + sbyte);
  }
}

// =====================================================================
// Kernel 1: conv3x3 s2 p1 (C1->C2) + BN1 + SiLU -> g_h (NHWC)
// CTA: 128 px (M) x 256 cout (N), 512 threads (16 warps: 4Mx4N).
// 18 chunks of 64 (tap=c>>1, ci0=(c&1)*64).
// =====================================================================
__global__ __launch_bounds__(512, 1)
void conv1_mma(const float* __restrict__ x,
               const float* __restrict__ bg, const float* __restrict__ bb,
               const float* __restrict__ bm, const float* __restrict__ bv)
{
  extern __shared__ char smem[];
  const uint32_t sb = smem_u32(smem);
  const int tid = threadIdx.x;
  const int n0 = blockIdx.x * 128;
  const int b  = n0 / SPIX;
  const int r0 = n0 - b * SPIX;

  if (tid < 128) {
    int r = r0 + tid, oh = r / HO, ow = r - oh * HO;
    ((int*)(smem + SM_META))[tid]       = 2*oh - 1;
    ((int*)(smem + SM_META + 512))[tid] = 2*ow - 1;
  }
  if (tid < 256) {
    float sc = bg[tid] * rsqrtf(bv[tid] + 1e-5f);
    ((float*)(smem + SM_BN))[tid]       = sc;
    ((float*)(smem + SM_BN + 1024))[tid] = bb[tid] - bm[tid] * sc;
  }
  __syncthreads();

  const int p   = tid & 127;   // gather pixel
  const int cig = tid >> 7;    // ci group (0..3) -> 16 ci each
  const int ihb = ((int*)(smem + SM_META))[p];
  const int iwb = ((int*)(smem + SM_META + 512))[p];
  const float* xb = x + (size_t)b * C1 * HIN * HIN;

  const int lane = tid & 31, wid = tid >> 5;
  const int mrow0 = (wid >> 2) * 32;   // px
  const int nrow0 = (wid & 3) * 64;    // cout

  float d[2][8][4];
  #pragma unroll
  for (int i = 0; i < 2; i++)
    #pragma unroll
    for (int j = 0; j < 8; j++)
      #pragma unroll
      for (int q = 0; q < 4; q++) d[i][j][q] = 0.0f;

  for (int c = 0; c < 18; c++) {
    const int k0 = c * 64, tap = c >> 1, ci0 = (c & 1) * 64;
    const int kh = tap / 3, kw = tap - 3 * kh;
    ld_W_chunk(smem, g_w1h, g_w1l, K1, k0, tid);
    // ---- pixel tile: im2col, 16 ci per thread (x is NCHW -> strided) ----
    const int ih = ihb + kh, iw = iwb + kw;
    const bool okp = ((unsigned)ih < (unsigned)HIN) && ((unsigned)iw < (unsigned)HIN);
    const float* src = xb + ih * HIN + iw + (size_t)(ci0 + cig*16) * (HIN*HIN);
    #pragma unroll
    for (int g = 0; g < 2; g++) {
      Pack8 hbuf, lbuf;
      #pragma unroll
      for (int j = 0; j < 8; j++) {
        float v = okp ? __ldg(src + (size_t)(g*8 + j) * (HIN*HIN)) : 0.0f;
        split_bf16(v, hbuf.s[j], lbuf.s[j]);
      }
      uint32_t doff = SWZ((uint32_t)(p*128 + cig*32 + g*16));
      *(uint4*)(smem + SM_P + doff)        = hbuf.v;
      *(uint4*)(smem + SM_P + P_LO + doff) = lbuf.v;
    }
    __syncthreads();
    chunk_mma<2,8>(sb, SM_P, P_LO, SM_W, W_LO, mrow0, nrow0, lane, d);
    __syncthreads();
  }

  // ---- epilogue: BN1 + SiLU, float2 NHWC stores (co pairs contiguous) ----
  const float* s_sc = (const float*)(smem + SM_BN);
  const float* s_sh = (const float*)(smem + SM_BN + 1024);
  float* dst = g_h + (size_t)b * SPIX * 256;
  #pragma unroll
  for (int mt = 0; mt < 2; mt++) {
    int px0 = r0 + mrow0 + mt*16 + (lane >> 2);
    #pragma unroll
    for (int nt = 0; nt < 8; nt++) {
      int co = nrow0 + nt*8 + (lane & 3)*2;
      float sc0 = s_sc[co], sh0 = s_sh[co];
      float sc1 = s_sc[co+1], sh1 = s_sh[co+1];
      float2 v0 = make_float2(silu_f(fmaf(d[mt][nt][0], sc0, sh0)),
                              silu_f(fmaf(d[mt][nt][1], sc1, sh1)));
      float2 v1 = make_float2(silu_f(fmaf(d[mt][nt][2], sc0, sh0)),
                              silu_f(fmaf(d[mt][nt][3], sc1, sh1)));
      *(float2*)(dst + (size_t)px0 * 256 + co)       = v0;
      *(float2*)(dst + (size_t)(px0 + 8) * 256 + co) = v1;
    }
  }
}

// =====================================================================
// Kernel 2: offset conv3x3 s1 p1 (C2->18) + bias -> g_off
// NHWC g_h: tap-major K, 16 contiguous ci per chunk via float4 loads.
// =====================================================================
__device__ __forceinline__ unsigned long long pack2(float v) {
  unsigned long long r;
  asm("mov.b64 %0, {%1, %1};" : "=l"(r) : "r"(__float_as_uint(v)));
  return r;
}
__device__ __forceinline__ void ffma2(unsigned long long &d, unsigned long long a,
                                      unsigned long long b) {
  asm("fma.rn.f32x2 %0, %1, %2, %0;" : "+l"(d) : "l"(a), "l"(b));
}
__device__ __forceinline__ float2 unpack2(unsigned long long v) {
  unsigned int lo, hi;
  asm("mov.b64 {%0, %1}, %2;" : "=r"(lo), "=r"(hi) : "l"(v));
  return make_float2(__uint_as_float(lo), __uint_as_float(hi));
}

__global__ __launch_bounds__(256)
void offs_kernel(const float* __restrict__ w, const float* __restrict__ bias)
{
  __shared__ __align__(16) float Ws[16][18];
  __shared__ __align__(16) float Xs[16][256];

  const int tid = threadIdx.x;
  const int n0  = blockIdx.x * 256;
  const int n   = n0 + tid;
  const int b   = n / SPIX;
  const int r   = n - b * SPIX;
  const int oh  = r / HO, ow = r - oh * HO;
  const int my_r = b * (18 * SPIX) + r;
  const float* hb = g_h + (size_t)b * SPIX * 256;

  unsigned long long acc[9];
  #pragma unroll
  for (int i = 0; i < 9; i++) acc[i] = 0ull;

  for (int tap = 0; tap < 9; tap++) {
    const int kh = tap / 3, kw = tap - 3 * kh;
    const int ih = oh + kh - 1, iw = ow + kw - 1;
    const bool ok = ((unsigned)ih < (unsigned)HO) && ((unsigned)iw < (unsigned)HO);
    const float* src = hb + (size_t)(ih * HO + iw) * 256;
    for (int ci0 = 0; ci0 < 256; ci0 += 16) {
      // weights: Ws[kk][co] = w[co][ (ci0+kk)*9 + tap ]
      {
        int e = tid;
        if (e < 288) {
          int co = e / 16, kk = e - co*16;
          Ws[kk][co] = w[co * K3 + (ci0 + kk) * 9 + tap];
        }
        e = tid + 256;
        if (e < 288) {
          int co = e / 16, kk = e - co*16;
          Ws[kk][co] = w[co * K3 + (ci0 + kk) * 9 + tap];
        }
      }
      // gather 16 contiguous ci
      float4 v[4];
      if (ok) {
        #pragma unroll
        for (int i = 0; i < 4; i++) v[i] = *(const float4*)(src + ci0 + i*4);
      } else {
        #pragma unroll
        for (int i = 0; i < 4; i++) v[i] = make_float4(0.f,0.f,0.f,0.f);
      }
      __syncthreads();
      #pragma unroll
      for (int i = 0; i < 4; i++) {
        Xs[i*4+0][tid] = v[i].x; Xs[i*4+1][tid] = v[i].y;
        Xs[i*4+2][tid] = v[i].z; Xs[i*4+3][tid] = v[i].w;
      }
      __syncthreads();
      #pragma unroll
      for (int kk = 0; kk < 16; kk++) {
        unsigned long long xp = pack2(Xs[kk][tid]);
        const unsigned long long* wr = reinterpret_cast<const unsigned long long*>(&Ws[kk][0]);
        #pragma unroll
        for (int i = 0; i < 9; i++) ffma2(acc[i], wr[i], xp);
      }
      __syncthreads();
    }
  }

  #pragma unroll
  for (int i = 0; i < 9; i++) {
    float2 v = unpack2(acc[i]);
    g_off[my_r + (2 * i    ) * SPIX] = v.x + bias[2 * i    ];
    g_off[my_r + (2 * i + 1) * SPIX] = v.y + bias[2 * i + 1];
  }
}

// =====================================================================
// Kernel 3: deformable conv3x3 + BN2 + SiLU -> out (NCHW)
// CTA: 256 cout (M) x 128 px (N), 512 threads. 36 chunks of 64 (tap=c>>2).
// Gather: NHWC g_h, 4 corners x 4 float4 per thread (16 ci).
// =====================================================================
__global__ __launch_bounds__(512, 1)
void deform_mma(const float* __restrict__ bg, const float* __restrict__ bb,
                const float* __restrict__ bm, const float* __restrict__ bv,
                float* __restrict__ out)
{
  extern __shared__ char smem[];
  const uint32_t sb = smem_u32(smem);
  const int tid = threadIdx.x;
  const int n0 = blockIdx.x * 128;
  const int b  = n0 / SPIX;
  const int r0 = n0 - b * SPIX;

  if (tid < 256) {
    float sc = bg[tid] * rsqrtf(bv[tid] + 1e-5f);
    ((float*)(smem + SM_BN))[tid]        = sc;
    ((float*)(smem + SM_BN + 1024))[tid] = bb[tid] - bm[tid] * sc;
  }
  // bilinear corner tables per (tap, pixel); offsets premultiplied by 256 (NHWC)
  for (int e = tid; e < 9 * 128; e += 512) {
    int tap = e >> 7, p = e & 127;
    int r = r0 + p;
    int oh = r / HO, ow = r - oh * HO;
    int kh = tap / 3, kw = tap - 3 * kh;
    float dy = g_off[((size_t)b*18 + 2*tap    ) * SPIX + r];
    float dx = g_off[((size_t)b*18 + 2*tap + 1) * SPIX + r];
    float py = (float)(oh + kh - 1) + dy;
    float px = (float)(ow + kw - 1) + dx;
    float fy = floorf(py), fx = floorf(px);
    int   y0 = (int)fy,    x0 = (int)fx;
    float wy1 = py - fy, wx1 = px - fx;
    float wy0 = 1.0f - wy1, wx0 = 1.0f - wx1;
    int*   to = (int*)  (smem + SM_TOF + e*16);
    float* tw = (float*)(smem + SM_TWT + e*16);
    #pragma unroll
    for (int q = 0; q < 4; q++) {
      int yy = y0 + (q >> 1);
      int xx = x0 + (q & 1);
      float wq = ((q >> 1) ? wy1 : wy0) * ((q & 1) ? wx1 : wx0);
      bool okq = (yy >= 0) && (yy < HO) && (xx >= 0) && (xx < HO);
      int yc = min(max(yy, 0), HO - 1);
      int xc = min(max(xx, 0), HO - 1);
      to[q] = (yc * HO + xc) * 256;
      tw[q] = okq ? wq : 0.0f;
    }
  }
  __syncthreads();

  const int p   = tid & 127;
  const int cig = tid >> 7;      // 16 ci per thread
  const float* hbase = g_h + (size_t)b * SPIX * 256;

  const int lane = tid & 31, wid = tid >> 5;
  const int mrow0 = (wid >> 2) * 64;   // cout
  const int nrow0 = (wid & 3) * 32;    // px

  float d[4][4][4];
  #pragma unroll
  for (int i = 0; i < 4; i++)
    #pragma unroll
    for (int j = 0; j < 4; j++)
      #pragma unroll
      for (int q = 0; q < 4; q++) d[i][j][q] = 0.0f;

  for (int c = 0; c < 36; c++) {
    const int k0 = c * 64, tap = c >> 2, ci0 = (c & 3) * 64;
    ld_W_chunk(smem, g_wdh, g_wdl, K3, k0, tid);
    // ---- pixel tile: bilinear gather, 16 contiguous ci per thread ----
    const int4   o4 = *(const int4*)  (smem + SM_TOF + (tap*128 + p)*16);
    const float4 w4 = *(const float4*)(smem + SM_TWT + (tap*128 + p)*16);
    const float* basep = hbase + ci0 + cig*16;
    float a[16];
    #pragma unroll
    for (int i = 0; i < 16; i++) a[i] = 0.0f;
    #pragma unroll
    for (int q = 0; q < 4; q++) {
      const float* cp = basep + (q == 0 ? o4.x : q == 1 ? o4.y : q == 2 ? o4.z : o4.w);
      float wq = (q == 0 ? w4.x : q == 1 ? w4.y : q == 2 ? w4.z : w4.w);
      #pragma unroll
      for (int i = 0; i < 4; i++) {
        float4 v = *(const float4*)(cp + i*4);
        a[i*4+0] = fmaf(wq, v.x, a[i*4+0]);
        a[i*4+1] = fmaf(wq, v.y, a[i*4+1]);
        a[i*4+2] = fmaf(wq, v.z, a[i*4+2]);
        a[i*4+3] = fmaf(wq, v.w, a[i*4+3]);
      }
    }
    #pragma unroll
    for (int g = 0; g < 2; g++) {
      Pack8 hbuf, lbuf;
      #pragma unroll
      for (int j = 0; j < 8; j++) split_bf16(a[g*8 + j], hbuf.s[j], lbuf.s[j]);
      uint32_t doff = SWZ((uint32_t)(p*128 + cig*32 + g*16));
      *(uint4*)(smem + SM_P + doff)        = hbuf.v;
      *(uint4*)(smem + SM_P + P_LO + doff) = lbuf.v;
    }
    __syncthreads();
    chunk_mma<4,4>(sb, SM_W, W_LO, SM_P, P_LO, mrow0, nrow0, lane, d);
    __syncthreads();
  }

  // ---- epilogue: BN2 + SiLU, float2 stores (NCHW, px pairs contiguous) ----
  const float* s_sc = (const float*)(smem + SM_BN);
  const float* s_sh = (const float*)(smem + SM_BN + 1024);
  const int group = lane >> 2, tig = lane & 3;
  float* dst = out + (size_t)b * C2 * SPIX;
  #pragma unroll
  for (int mt = 0; mt < 4; mt++) {
    int co0 = mrow0 + mt*16 + group, co1 = co0 + 8;
    float s0 = s_sc[co0], h0 = s_sh[co0];
    float s1 = s_sc[co1], h1 = s_sh[co1];
    #pragma unroll
    for (int nt = 0; nt < 4; nt++) {
      int px = r0 + nrow0 + nt*8 + tig*2;
      float2 v0 = make_float2(silu_f(fmaf(d[mt][nt][0], s0, h0)),
                              silu_f(fmaf(d[mt][nt][1], s0, h0)));
      float2 v1 = make_float2(silu_f(fmaf(d[mt][nt][2], s1, h1)),
                              silu_f(fmaf(d[mt][nt][3], s1, h1)));
      *(float2*)(dst + (size_t)co0 * SPIX + px) = v0;
      *(float2*)(dst + (size_t)co1 * SPIX + px) = v1;
    }
  }
}

// =====================================================================
extern "C" void kernel_launch(void* const* d_in, const int* in_sizes, int n_in,
                              void* d_out, int out_size) {
  const float* x       = (const float*)d_in[0];
  const float* conv1_w = (const float*)d_in[1];
  const float* bn1_g   = (const float*)d_in[2];
  const float* bn1_b   = (const float*)d_in[3];
  const float* bn1_m   = (const float*)d_in[4];
  const float* bn1_v   = (const float*)d_in[5];
  const float* off_w   = (const float*)d_in[6];
  const float* off_b   = (const float*)d_in[7];
  const float* dconv_w = (const float*)d_in[8];
  const float* bn2_g   = (const float*)d_in[9];
  const float* bn2_b   = (const float*)d_in[10];
  const float* bn2_m   = (const float*)d_in[11];
  const float* bn2_v   = (const float*)d_in[12];
  float* out = (float*)d_out;

  cudaFuncSetAttribute(conv1_mma,  cudaFuncAttributeMaxDynamicSharedMemorySize, SMEM_CONV1);
  cudaFuncSetAttribute(deform_mma, cudaFuncAttributeMaxDynamicSharedMemorySize, SMEM_DEFORM);

  prep_kernel<<<512, 256>>>(conv1_w, dconv_w);
  conv1_mma<<<NPIX / 128, 512, SMEM_CONV1>>>(x, bn1_g, bn1_b, bn1_m, bn1_v);
  offs_kernel<<<NPIX / 256, 256>>>(off_w, off_b);
  deform_mma<<<NPIX / 128, 512, SMEM_DEFORM>>>(bn2_g, bn2_b, bn2_m, bn2_v, out);
}

// round 11
// speedup vs baseline: 1.1490x; 1.1490x over previous
#include <cuda_runtime.h>
#include <cuda_bf16.h>
#include <cstdint>

#define BATCH 8
#define C1    128
#define C2    256
#define HIN   160
#define HO    80
#define SPIX  6400
#define NPIX  51200
#define K1    1152
#define K3    2304

// -------- scratch (device globals; no runtime allocation) --------
__device__ float g_h  [BATCH*C2*SPIX];   // NCHW: [b][ci][pixel]
__device__ float g_off[BATCH*18*SPIX];   // offsets
__device__ __nv_bfloat16 g_w1h[C2*K1];   // conv1 weights, k=tap*128+ci, hi
__device__ __nv_bfloat16 g_w1l[C2*K1];   // lo
__device__ __nv_bfloat16 g_wdh[C2*K3];   // deform weights, k=tap*256+ci, hi
__device__ __nv_bfloat16 g_wdl[C2*K3];   // lo

// -------- helpers --------
__device__ __forceinline__ uint32_t smem_u32(const void* p){
  uint32_t a;
  asm("{ .reg .u64 t; cvta.to.shared.u64 t, %1; cvt.u32.u64 %0, t; }" : "=r"(a) : "l"(p));
  return a;
}
#define SWZ(o) ((o) ^ (((o)>>3)&0x70))

__device__ __forceinline__ void ldsm4(uint32_t* r, uint32_t addr){
  asm volatile("ldmatrix.sync.aligned.m8n8.x4.shared.b16 {%0,%1,%2,%3}, [%4];"
    : "=r"(r[0]),"=r"(r[1]),"=r"(r[2]),"=r"(r[3]) : "r"(addr));
}
__device__ __forceinline__ void ldsm2(uint32_t* r, uint32_t addr){
  asm volatile("ldmatrix.sync.aligned.m8n8.x2.shared.b16 {%0,%1}, [%2];"
    : "=r"(r[0]),"=r"(r[1]) : "r"(addr));
}
__device__ __forceinline__ void mma16816(float* d, const uint32_t* a, const uint32_t* b){
  asm volatile("mma.sync.aligned.m16n8k16.row.col.f32.bf16.bf16.f32 "
    "{%0,%1,%2,%3}, {%4,%5,%6,%7}, {%8,%9}, {%0,%1,%2,%3};"
    : "+f"(d[0]), "+f"(d[1]), "+f"(d[2]), "+f"(d[3])
    : "r"(a[0]), "r"(a[1]), "r"(a[2]), "r"(a[3]), "r"(b[0]), "r"(b[1]));
}

union Pack8 { unsigned short s[8]; uint4 v; };

__device__ __forceinline__ float silu_f(float v) {
  return __fdividef(v, 1.0f + __expf(-v));
}
__device__ __forceinline__ void split_bf16(float v, unsigned short& h, unsigned short& l){
  __nv_bfloat16 hh = __float2bfloat16(v);
  float hf = __bfloat162float(hh);
  __nv_bfloat16 ll = __float2bfloat16(v - hf);
  h = __bfloat16_as_ushort(hh);
  l = __bfloat16_as_ushort(ll);
}

// SMEM layout (byte offsets within dynamic smem)
// W tile: 128 co-rows x 128B hi (16KB) + lo (16KB)
#define SM_W    0
#define W_LO    16384
// P tile: 128 px-rows x 128B hi (16KB) + lo (16KB)
#define SM_P    32768
#define P_LO    16384
#define SM_BN   65536    // scale[256] + shift[256]
#define SM_META 67584              // conv1: ih[128], iw[128]
#define SM_TOF  67584              // deform: t_off 9*128*16B
#define SM_TWT  (67584+18432)      // deform: t_wt  9*128*16B
#define SMEM_CONV1  68608
#define SMEM_DEFORM 104448

// =====================================================================
// Prep: convert+reorder weights to bf16 hi/lo, k = tap*Cin + ci
// =====================================================================
__global__ void prep_kernel(const float* __restrict__ w1, const float* __restrict__ wd)
{
  int stride = gridDim.x * blockDim.x;
  for (int i = blockIdx.x*blockDim.x + threadIdx.x; i < C2*K1; i += stride) {
    int co = i / K1, t = i - co*K1, tap = t >> 7, ci = t & 127;
    float v = w1[(co*C1 + ci)*9 + tap];
    unsigned short h, l; split_bf16(v, h, l);
    g_w1h[i] = __ushort_as_bfloat16(h);
    g_w1l[i] = __ushort_as_bfloat16(l);
  }
  for (int i = blockIdx.x*blockDim.x + threadIdx.x; i < C2*K3; i += stride) {
    int co = i / K3, t = i - co*K3, tap = t >> 8, ci = t & 255;
    float v = wd[(co*C2 + ci)*9 + tap];
    unsigned short h, l; split_bf16(v, h, l);
    g_wdh[i] = __ushort_as_bfloat16(h);
    g_wdl[i] = __ushort_as_bfloat16(l);
  }
}

// =====================================================================
// Chunk MMA: K=64 (4 ksteps). M operand (ldsm4) = W tile rows (couts),
// N operand (ldsm2) = P tile rows (pixels). 3-product bf16 hi/lo split.
// Warp tile 64co x 32px; 8 warps: 2(M) x 4(N).
// =====================================================================
__device__ __forceinline__ void chunk_mma(uint32_t sb, int mrow0, int nrow0,
                                          int lane, float d[4][4][4])
{
  #pragma unroll
  for (int ks = 0; ks < 4; ks++) {
    uint32_t bh[4][2], bl[4][2];
    const uint32_t bcol = ks*32 + ((lane >> 3) & 1) * 16;
    #pragma unroll
    for (int nt = 0; nt < 4; nt++) {
      uint32_t bo = SWZ((uint32_t)(nrow0 + nt*8 + (lane & 7)) * 128 + bcol);
      ldsm2(bh[nt], sb + SM_P + bo);
      ldsm2(bl[nt], sb + SM_P + P_LO + bo);
    }
    const uint32_t acol = ks*32 + ((lane >> 4) & 1) * 16;
    #pragma unroll
    for (int mt = 0; mt < 4; mt++) {
      uint32_t ah[4], al[4];
      uint32_t ao = SWZ((uint32_t)(mrow0 + mt*16 + (lane & 15)) * 128 + acol);
      ldsm4(ah, sb + SM_W + ao);
      ldsm4(al, sb + SM_W + W_LO + ao);
      #pragma unroll
      for (int nt = 0; nt < 4; nt++) {
        mma16816(d[mt][nt], ah, bh[nt]);
        mma16816(d[mt][nt], ah, bl[nt]);
        mma16816(d[mt][nt], al, bh[nt]);
      }
    }
  }
}

// Weight tile loader: 128 rows x 64 k (hi+lo), 128B rows, swizzled. 256 thr.
__device__ __forceinline__ void ld_W_chunk(char* smem,
    const __nv_bfloat16* wh, const __nv_bfloat16* wl, int K, int k0,
    int co0, int tid)
{
  #pragma unroll
  for (int i = 0; i < 4; i++) {
    int e = tid + i*256;              // 0..1023
    int row = e >> 3, col = e & 7;
    size_t sbyte = ((size_t)(co0 + row) * K + k0) * 2 + col * 16;
    uint32_t doff = SWZ((uint32_t)(row*128 + col*16));
    *(uint4*)(smem + SM_W + doff)        = *(const uint4*)((const char*)wh + sbyte);
    *(uint4*)(smem + SM_W + W_LO + doff) = *(const uint4*)((const char*)wl + sbyte);
  }
}

// =====================================================================
// Kernel 1: conv3x3 s2 p1 (C1->C2) + BN1 + SiLU -> g_h (NCHW)
// CTA: 128 co (blockIdx.y half) x 128 px, 256 threads, 2 CTAs/SM.
// 18 chunks of 64 (tap=c>>1, ci0=(c&1)*64).
// =====================================================================
__global__ __launch_bounds__(256, 2)
void conv1_mma(const float* __restrict__ x,
               const float* __restrict__ bg, const float* __restrict__ bb,
               const float* __restrict__ bm, const float* __restrict__ bv)
{
  extern __shared__ char smem[];
  const uint32_t sb = smem_u32(smem);
  const int tid = threadIdx.x;
  const int n0 = blockIdx.x * 128;
  const int b  = n0 / SPIX;
  const int r0 = n0 - b * SPIX;
  const int co0 = blockIdx.y * 128;

  if (tid < 128) {
    int r = r0 + tid, oh = r / HO, ow = r - oh * HO;
    ((int*)(smem + SM_META))[tid]       = 2*oh - 1;
    ((int*)(smem + SM_META + 512))[tid] = 2*ow - 1;
  }
  {
    float sc = bg[tid] * rsqrtf(bv[tid] + 1e-5f);
    ((float*)(smem + SM_BN))[tid]        = sc;
    ((float*)(smem + SM_BN + 1024))[tid] = bb[tid] - bm[tid] * sc;
  }
  __syncthreads();

  const int p   = tid & 127;   // gather pixel
  const int cig = tid >> 7;    // ci group (0..1) -> 32 ci each
  const int ihb = ((int*)(smem + SM_META))[p];
  const int iwb = ((int*)(smem + SM_META + 512))[p];
  const float* xb = x + (size_t)b * C1 * HIN * HIN;

  const int lane = tid & 31, wid = tid >> 5;
  const int mrow0 = (wid >> 2) * 64;   // co within 128
  const int nrow0 = (wid & 3) * 32;    // px

  float d[4][4][4];
  #pragma unroll
  for (int i = 0; i < 4; i++)
    #pragma unroll
    for (int j = 0; j < 4; j++)
      #pragma unroll
      for (int q = 0; q < 4; q++) d[i][j][q] = 0.0f;

  for (int c = 0; c < 18; c++) {
    const int k0 = c * 64, tap = c >> 1, ci0 = (c & 1) * 64;
    const int kh = tap / 3, kw = tap - 3 * kh;
    ld_W_chunk(smem, g_w1h, g_w1l, K1, k0, co0, tid);
    // ---- pixel tile: im2col, 32 ci per thread ----
    const int ih = ihb + kh, iw = iwb + kw;
    const bool okp = ((unsigned)ih < (unsigned)HIN) && ((unsigned)iw < (unsigned)HIN);
    const float* src = xb + ih * HIN + iw + (size_t)(ci0 + cig*32) * (HIN*HIN);
    #pragma unroll
    for (int g = 0; g < 4; g++) {
      Pack8 hbuf, lbuf;
      #pragma unroll
      for (int j = 0; j < 8; j++) {
        float v = okp ? __ldg(src + (size_t)(g*8 + j) * (HIN*HIN)) : 0.0f;
        split_bf16(v, hbuf.s[j], lbuf.s[j]);
      }
      uint32_t doff = SWZ((uint32_t)(p*128 + cig*64 + g*16));
      *(uint4*)(smem + SM_P + doff)        = hbuf.v;
      *(uint4*)(smem + SM_P + P_LO + doff) = lbuf.v;
    }
    __syncthreads();
    chunk_mma(sb, mrow0, nrow0, lane, d);
    __syncthreads();
  }

  // ---- epilogue: BN1 + SiLU, float2 px-pair stores (NCHW) ----
  const float* s_sc = (const float*)(smem + SM_BN);
  const float* s_sh = (const float*)(smem + SM_BN + 1024);
  const int group = lane >> 2, tig = lane & 3;
  float* dst = g_h + (size_t)b * C2 * SPIX;
  #pragma unroll
  for (int mt = 0; mt < 4; mt++) {
    int ca = co0 + mrow0 + mt*16 + group, cb = ca + 8;
    float s0 = s_sc[ca], h0 = s_sh[ca];
    float s1 = s_sc[cb], h1 = s_sh[cb];
    #pragma unroll
    for (int nt = 0; nt < 4; nt++) {
      int px = r0 + nrow0 + nt*8 + tig*2;
      float2 v0 = make_float2(silu_f(fmaf(d[mt][nt][0], s0, h0)),
                              silu_f(fmaf(d[mt][nt][1], s0, h0)));
      float2 v1 = make_float2(silu_f(fmaf(d[mt][nt][2], s1, h1)),
                              silu_f(fmaf(d[mt][nt][3], s1, h1)));
      *(float2*)(dst + (size_t)ca * SPIX + px) = v0;
      *(float2*)(dst + (size_t)cb * SPIX + px) = v1;
    }
  }
}

// =====================================================================
// Kernel 2: offset conv3x3 s1 p1 (C2->18) + bias -> g_off (scalar f32x2)
// =====================================================================
__device__ __forceinline__ unsigned long long pack2(float v) {
  unsigned long long r;
  asm("mov.b64 %0, {%1, %1};" : "=l"(r) : "r"(__float_as_uint(v)));
  return r;
}
__device__ __forceinline__ void ffma2(unsigned long long &d, unsigned long long a,
                                      unsigned long long b) {
  asm("fma.rn.f32x2 %0, %1, %2, %0;" : "+l"(d) : "l"(a), "l"(b));
}
__device__ __forceinline__ float2 unpack2(unsigned long long v) {
  unsigned int lo, hi;
  asm("mov.b64 {%0, %1}, %2;" : "=r"(lo), "=r"(hi) : "l"(v));
  return make_float2(__uint_as_float(lo), __uint_as_float(hi));
}

__global__ __launch_bounds__(256)
void offs_kernel(const float* __restrict__ w, const float* __restrict__ bias)
{
  __shared__ __align__(16) float Ws[16][18];
  __shared__ __align__(16) float Xs[16][256];
  __shared__ int s_hb[256], s_ihb[256], s_iwb[256], s_r[256];

  const int tid = threadIdx.x;
  const int n0  = blockIdx.x * 256;
  {
    int n  = n0 + tid;
    int b  = n / SPIX;
    int r  = n - b * SPIX;
    int oh = r / HO, ow = r - oh * HO;
    s_hb [tid] = b * (C2 * SPIX);
    s_ihb[tid] = oh - 1;
    s_iwb[tid] = ow - 1;
    s_r  [tid] = b * (18 * SPIX) + r;
  }
  __syncthreads();
  const int my_hb = s_hb[tid], my_ihb = s_ihb[tid], my_iwb = s_iwb[tid];
  const int my_r  = s_r[tid];

  unsigned long long acc[9];
  #pragma unroll
  for (int i = 0; i < 9; i++) acc[i] = 0ull;

  for (int k0 = 0; k0 < K3; k0 += 16) {
    for (int e = tid; e < 18 * 16; e += 256) {
      int co = e >> 4, kk = e & 15;
      Ws[kk][co] = w[co * K3 + k0 + kk];
    }
    #pragma unroll 4
    for (int kk = 0; kk < 16; kk++) {
      int k  = k0 + kk;
      int ci = k / 9;
      int t  = k - ci * 9;
      int kh = t / 3, kw = t - kh * 3;
      int ih = my_ihb + kh, iw = my_iwb + kw;
      float val = 0.0f;
      if ((unsigned)ih < (unsigned)HO && (unsigned)iw < (unsigned)HO)
        val = g_h[my_hb + ci * SPIX + ih * HO + iw];
      Xs[kk][tid] = val;
    }
    __syncthreads();
    #pragma unroll
    for (int kk = 0; kk < 16; kk++) {
      unsigned long long xp = pack2(Xs[kk][tid]);
      const unsigned long long* wr = reinterpret_cast<const unsigned long long*>(&Ws[kk][0]);
      #pragma unroll
      for (int i = 0; i < 9; i++) ffma2(acc[i], wr[i], xp);
    }
    __syncthreads();
  }

  #pragma unroll
  for (int i = 0; i < 9; i++) {
    float2 v = unpack2(acc[i]);
    g_off[my_r + (2 * i    ) * SPIX] = v.x + bias[2 * i    ];
    g_off[my_r + (2 * i + 1) * SPIX] = v.y + bias[2 * i + 1];
  }
}

// =====================================================================
// Kernel 3: deformable conv3x3 + BN2 + SiLU -> out (NCHW)
// CTA: 128 co (blockIdx.y half) x 128 px, 256 threads, 2 CTAs/SM.
// 36 chunks of 64 (tap=c>>2, ci0=(c&3)*64).
// =====================================================================
__global__ __launch_bounds__(256, 2)
void deform_mma(const float* __restrict__ bg, const float* __restrict__ bb,
                const float* __restrict__ bm, const float* __restrict__ bv,
                float* __restrict__ out)
{
  extern __shared__ char smem[];
  const uint32_t sb = smem_u32(smem);
  const int tid = threadIdx.x;
  const int n0 = blockIdx.x * 128;
  const int b  = n0 / SPIX;
  const int r0 = n0 - b * SPIX;
  const int co0 = blockIdx.y * 128;

  {
    float sc = bg[tid] * rsqrtf(bv[tid] + 1e-5f);
    ((float*)(smem + SM_BN))[tid]        = sc;
    ((float*)(smem + SM_BN + 1024))[tid] = bb[tid] - bm[tid] * sc;
  }
  // bilinear corner tables per (tap, pixel)
  for (int e = tid; e < 9 * 128; e += 256) {
    int tap = e >> 7, p = e & 127;
    int r = r0 + p;
    int oh = r / HO, ow = r - oh * HO;
    int kh = tap / 3, kw = tap - 3 * kh;
    float dy = g_off[((size_t)b*18 + 2*tap    ) * SPIX + r];
    float dx = g_off[((size_t)b*18 + 2*tap + 1) * SPIX + r];
    float py = (float)(oh + kh - 1) + dy;
    float px = (float)(ow + kw - 1) + dx;
    float fy = floorf(py), fx = floorf(px);
    int   y0 = (int)fy,    x0 = (int)fx;
    float wy1 = py - fy, wx1 = px - fx;
    float wy0 = 1.0f - wy1, wx0 = 1.0f - wx1;
    int*   to = (int*)  (smem + SM_TOF + e*16);
    float* tw = (float*)(smem + SM_TWT + e*16);
    #pragma unroll
    for (int q = 0; q < 4; q++) {
      int yy = y0 + (q >> 1);
      int xx = x0 + (q & 1);
      float wq = ((q >> 1) ? wy1 : wy0) * ((q & 1) ? wx1 : wx0);
      bool okq = (yy >= 0) && (yy < HO) && (xx >= 0) && (xx < HO);
      int yc = min(max(yy, 0), HO - 1);
      int xc = min(max(xx, 0), HO - 1);
      to[q] = yc * HO + xc;
      tw[q] = okq ? wq : 0.0f;
    }
  }
  __syncthreads();

  const int p   = tid & 127;
  const int cig = tid >> 7;      // 32 ci per thread
  const float* hbase = g_h + (size_t)b * C2 * SPIX;

  const int lane = tid & 31, wid = tid >> 5;
  const int mrow0 = (wid >> 2) * 64;
  const int nrow0 = (wid & 3) * 32;

  float d[4][4][4];
  #pragma unroll
  for (int i = 0; i < 4; i++)
    #pragma unroll
    for (int j = 0; j < 4; j++)
      #pragma unroll
      for (int q = 0; q < 4; q++) d[i][j][q] = 0.0f;

  for (int c = 0; c < 36; c++) {
    const int k0 = c * 64, tap = c >> 2, ci0 = (c & 3) * 64;
    ld_W_chunk(smem, g_wdh, g_wdl, K3, k0, co0, tid);
    // ---- pixel tile: bilinear gather, 32 ci per thread ----
    const int4   o4 = *(const int4*)  (smem + SM_TOF + (tap*128 + p)*16);
    const float4 w4 = *(const float4*)(smem + SM_TWT + (tap*128 + p)*16);
    #pragma unroll
    for (int g = 0; g < 4; g++) {
      Pack8 hbuf, lbuf;
      #pragma unroll
      for (int j = 0; j < 8; j++) {
        const float* pp = hbase + (size_t)(ci0 + cig*32 + g*8 + j) * SPIX;
        float v = w4.x * __ldg(pp + o4.x) + w4.y * __ldg(pp + o4.y)
                + w4.z * __ldg(pp + o4.z) + w4.w * __ldg(pp + o4.w);
        split_bf16(v, hbuf.s[j], lbuf.s[j]);
      }
      uint32_t doff = SWZ((uint32_t)(p*128 + cig*64 + g*16));
      *(uint4*)(smem + SM_P + doff)        = hbuf.v;
      *(uint4*)(smem + SM_P + P_LO + doff) = lbuf.v;
    }
    __syncthreads();
    chunk_mma(sb, mrow0, nrow0, lane, d);
    __syncthreads();
  }

  // ---- epilogue: BN2 + SiLU, float2 px-pair stores (NCHW) ----
  const float* s_sc = (const float*)(smem + SM_BN);
  const float* s_sh = (const float*)(smem + SM_BN + 1024);
  const int group = lane >> 2, tig = lane & 3;
  float* dst = out + (size_t)b * C2 * SPIX;
  #pragma unroll
  for (int mt = 0; mt < 4; mt++) {
    int ca = co0 + mrow0 + mt*16 + group, cb = ca + 8;
    float s0 = s_sc[ca], h0 = s_sh[ca];
    float s1 = s_sc[cb], h1 = s_sh[cb];
    #pragma unroll
    for (int nt = 0; nt < 4; nt++) {
      int px = r0 + nrow0 + nt*8 + tig*2;
      float2 v0 = make_float2(silu_f(fmaf(d[mt][nt][0], s0, h0)),
                              silu_f(fmaf(d[mt][nt][1], s0, h0)));
      float2 v1 = make_float2(silu_f(fmaf(d[mt][nt][2], s1, h1)),
                              silu_f(fmaf(d[mt][nt][3], s1, h1)));
      *(float2*)(dst + (size_t)ca * SPIX + px) = v0;
      *(float2*)(dst + (size_t)cb * SPIX + px) = v1;
    }
  }
}

// =====================================================================
extern "C" void kernel_launch(void* const* d_in, const int* in_sizes, int n_in,
                              void* d_out, int out_size) {
  const float* x       = (const float*)d_in[0];
  const float* conv1_w = (const float*)d_in[1];
  const float* bn1_g   = (const float*)d_in[2];
  const float* bn1_b   = (const float*)d_in[3];
  const float* bn1_m   = (const float*)d_in[4];
  const float* bn1_v   = (const float*)d_in[5];
  const float* off_w   = (const float*)d_in[6];
  const float* off_b   = (const float*)d_in[7];
  const float* dconv_w = (const float*)d_in[8];
  const float* bn2_g   = (const float*)d_in[9];
  const float* bn2_b   = (const float*)d_in[10];
  const float* bn2_m   = (const float*)d_in[11];
  const float* bn2_v   = (const float*)d_in[12];
  float* out = (float*)d_out;

  cudaFuncSetAttribute(conv1_mma,  cudaFuncAttributeMaxDynamicSharedMemorySize, SMEM_CONV1);
  cudaFuncSetAttribute(deform_mma, cudaFuncAttributeMaxDynamicSharedMemorySize, SMEM_DEFORM);

  prep_kernel<<<512, 256>>>(conv1_w, dconv_w);
  conv1_mma<<<dim3(NPIX / 128, 2), 256, SMEM_CONV1>>>(x, bn1_g, bn1_b, bn1_m, bn1_v);
  offs_kernel<<<NPIX / 256, 256>>>(off_w, off_b);
  deform_mma<<<dim3(NPIX / 128, 2), 256, SMEM_DEFORM>>>(bn2_g, bn2_b, bn2_m, bn2_v, out);
}